// round 4
// baseline (speedup 1.0000x reference)
#include <cuda_runtime.h>
#include <cstdint>

// Problem dims
#define BB 128      // batch
#define TT 1024     // seq
#define EE 512      // embed
#define HH 1024     // hidden
#define VV 512      // vocab

#define NB 128      // persistent blocks (<= 148 SMs, guaranteed co-resident)
#define NT 256      // threads per block

// ---------------- persistent device scratch (no allocations allowed) ----------------
__device__ __align__(16) float g_tokproj[VV * HH];                  // 2 MB: b_h0 + w_xh0 @ emb[v]
__device__ __align__(16) float g_part0[2][4][BB * HH];              // GEMM-A K-split partials (parity x 4)
__device__ __align__(16) float g_part1[2][4][BB * HH];              // GEMM-B K-split partials
__device__ __align__(16) float g_h0[BB * HH];                       // compact h0_t
__device__ __align__(16) float g_h1[BB * HH];                       // compact h1_{t-1}
__device__ __align__(16) float g_h1all[(size_t)TT * BB * HH];       // 512 MB: all h1 states for logits GEMM
__device__ unsigned long long g_arrive;                             // barrier arrival counter (monotonic)
__device__ unsigned long long g_epoch[NB];                          // per-block persistent epoch (replay-safe)

// ---------------- grid-wide barrier (software, replay-safe) ----------------
__device__ __forceinline__ void grid_bar(unsigned long long& epoch) {
    __syncthreads();
    if (threadIdx.x == 0) {
        __threadfence();
        atomicAdd(&g_arrive, 1ULL);
        epoch += (unsigned long long)NB;
        while (*(volatile unsigned long long*)&g_arrive < epoch) {
            __nanosleep(128);
        }
        __threadfence();
    }
    __syncthreads();
}

// ---------------- generic 64x64 tile GEMM: C[64,64] += sum_k A[m,k]*B[n,k] ----------------
// smem layout: s[k][r] with row stride 68 floats (conflict-light, float4-aligned reads)
template <typename LA, typename LB, typename ST>
__device__ __forceinline__ void gemm64(float* sA, float* sB, int kbeg, int kend,
                                       LA la, LB lb, ST st) {
    const int tid = threadIdx.x;
    const int tx = tid & 15;
    const int ty = tid >> 4;
    float acc[4][4];
#pragma unroll
    for (int i = 0; i < 4; i++)
#pragma unroll
        for (int j = 0; j < 4; j++) acc[i][j] = 0.f;

    for (int k0 = kbeg; k0 < kend; k0 += 32) {
        // stage 64x32 A-tile and B-tile, transposed to [k][r]
#pragma unroll
        for (int i = 0; i < 8; i++) {
            int idx = tid + i * NT;      // 0..2047
            int k = idx & 31;
            int r = idx >> 5;            // 0..63
            sA[k * 68 + r] = la(r, k0 + k);
            sB[k * 68 + r] = lb(r, k0 + k);
        }
        __syncthreads();
#pragma unroll
        for (int kk = 0; kk < 32; kk++) {
            float4 a = *(const float4*)(sA + kk * 68 + 4 * ty);
            float4 b = *(const float4*)(sB + kk * 68 + 4 * tx);
            float av[4] = {a.x, a.y, a.z, a.w};
            float bv[4] = {b.x, b.y, b.z, b.w};
#pragma unroll
            for (int i = 0; i < 4; i++)
#pragma unroll
                for (int j = 0; j < 4; j++)
                    acc[i][j] = fmaf(av[i], bv[j], acc[i][j]);
        }
        __syncthreads();
    }
#pragma unroll
    for (int i = 0; i < 4; i++) {
        float4 v = make_float4(acc[i][0], acc[i][1], acc[i][2], acc[i][3]);
        st(4 * ty + i, 4 * tx, v);
    }
}

// ---------------- the persistent RNN kernel ----------------
__global__ void __launch_bounds__(NT, 1) rnn_persistent_kernel(
    const int*   __restrict__ ids,     // [B,T]
    const float* __restrict__ emb,     // [V,E]
    const float* __restrict__ w_xh0,   // [H,E]
    const float* __restrict__ w_hh0,   // [H,H]
    const float* __restrict__ b_h0,    // [H]
    const float* __restrict__ w_xh1,   // [H,H]
    const float* __restrict__ w_hh1,   // [H,H]
    const float* __restrict__ b_h1,    // [H]
    const float* __restrict__ w_hy,    // [V,H]
    const float* __restrict__ b_y,     // [V]
    float* __restrict__ out,
    long long out_size)
{
    __shared__ float sA[32 * 68];
    __shared__ float sB[32 * 68];
    const int bid = blockIdx.x;
    const int tid = threadIdx.x;

    unsigned long long epoch = 0;
    if (tid == 0) epoch = g_epoch[bid];

    // ================= prologue =================
    // zero part0[parity 0] (needed at t=0) and g_h1 (h1_{-1} = 0)
    {
        float* z = &g_part0[0][0][0];   // 4 * B*H floats
        for (int i = tid; i < 4096; i += NT) z[bid * 4096 + i] = 0.f;
        for (int i = tid; i < 1024; i += NT) g_h1[bid * 1024 + i] = 0.f;
    }
    // tokproj[v][h] = b_h0[h] + sum_e emb[v][e] * w_xh0[h][e]
    {
        int mt = bid & 7;            // 8 m-tiles over V=512
        int nt = bid >> 3;           // 16 n-tiles over H=1024
        int m0 = mt * 64, n0 = nt * 64;
        gemm64(sA, sB, 0, EE,
            [&](int r, int k) { return emb[(m0 + r) * EE + k]; },
            [&](int r, int k) { return w_xh0[(n0 + r) * EE + k]; },
            [&](int m, int n, float4 v) {
                int col = n0 + n;
                float4 bb = *(const float4*)(b_h0 + col);
                v.x += bb.x; v.y += bb.y; v.z += bb.z; v.w += bb.w;
                *(float4*)(g_tokproj + (size_t)(m0 + m) * HH + col) = v;
            });
    }
    grid_bar(epoch);

    // ================= sequential loop =================
    for (int t = 0; t < TT; t++) {
        const int p = t & 1;
        const int q = p ^ 1;

        // ---- phase 1: GEMM A (pre0 partials) + finalize h1_{t-1} ----
        if (t > 0) {
            int mt = bid & 1;
            int nt = (bid >> 1) & 15;
            int kc = bid >> 5;
            int m0 = mt * 64, n0 = nt * 64;
            gemm64(sA, sB, kc * 256, kc * 256 + 256,
                [&](int r, int k) { return g_h0[(m0 + r) * HH + k]; },
                [&](int r, int k) { return w_hh0[(n0 + r) * HH + k]; },
                [&](int m, int n, float4 v) {
                    *(float4*)&g_part0[p][kc][(m0 + m) * HH + n0 + n] = v;
                });
            // h1_{t-1} = tanh(b_h1 + sum partials)  -> g_h1 (compact) + g_h1all[t-1]
            for (int i = tid; i < 1024; i += NT) {
                int idx = bid * 1024 + i;
                int k = idx & (HH - 1);
                float s = b_h1[k] + g_part1[q][0][idx] + g_part1[q][1][idx]
                                  + g_part1[q][2][idx] + g_part1[q][3][idx];
                float v = tanhf(s);
                g_h1[idx] = v;
                g_h1all[(size_t)(t - 1) * (BB * HH) + idx] = v;
            }
        }
        grid_bar(epoch);

        // ---- phase 2: GEMM B (pre1 partials) + finalize h0_t compact ----
        {
            int mt = bid & 1;
            int nt = (bid >> 1) & 15;
            int kc = bid >> 5;
            int m0 = mt * 64, n0 = nt * 64;
            int kbeg = kc * 512;
            auto stp = [&](int m, int n, float4 v) {
                *(float4*)&g_part1[p][kc][(m0 + m) * HH + n0 + n] = v;
            };
            if (kc < 2) {
                // first K-half: A = h0_t = tanh(tokproj[id] + sum part0[p])
                gemm64(sA, sB, kbeg, kbeg + 512,
                    [&](int r, int k) {
                        int b = m0 + r;
                        int id = ids[b * TT + t];
                        float s = g_tokproj[(size_t)id * HH + k]
                                + g_part0[p][0][b * HH + k] + g_part0[p][1][b * HH + k]
                                + g_part0[p][2][b * HH + k] + g_part0[p][3][b * HH + k];
                        return tanhf(s);
                    },
                    [&](int r, int k) { return w_xh1[(n0 + r) * HH + k]; },
                    stp);
            } else {
                // second K-half: A = h1_{t-1} (compact)
                gemm64(sA, sB, kbeg - 1024, kbeg - 1024 + 512,
                    [&](int r, int k) { return g_h1[(m0 + r) * HH + k]; },
                    [&](int r, int k) { return w_hh1[(n0 + r) * HH + k]; },
                    stp);
            }
            // compact h0_t for next step's GEMM A
            for (int i = tid; i < 1024; i += NT) {
                int idx = bid * 1024 + i;
                int b = idx >> 10;
                int k = idx & (HH - 1);
                int id = ids[b * TT + t];
                float s = g_tokproj[(size_t)id * HH + k]
                        + g_part0[p][0][idx] + g_part0[p][1][idx]
                        + g_part0[p][2][idx] + g_part0[p][3][idx];
                g_h0[idx] = tanhf(s);
            }
        }
        grid_bar(epoch);
    }

    // ================= epilogue =================
    // finalize h1_{T-1} (p=1 at t=1023), write final states if requested
    {
        const long long full = (long long)BB * TT * VV + 2LL * BB * HH;
        for (int i = tid; i < 1024; i += NT) {
            int idx = bid * 1024 + i;
            int k = idx & (HH - 1);
            float s = b_h1[k] + g_part1[1][0][idx] + g_part1[1][1][idx]
                              + g_part1[1][2][idx] + g_part1[1][3][idx];
            float v = tanhf(s);
            g_h1all[(size_t)(TT - 1) * (BB * HH) + idx] = v;
            if (out_size >= full) {
                out[(size_t)BB * TT * VV + idx] = g_h0[idx];            // h0 final
                out[(size_t)BB * TT * VV + BB * HH + idx] = v;           // h1 final
            }
        }
    }
    grid_bar(epoch);
    if (tid == 0) g_epoch[bid] = epoch;   // persist epoch for next replay

    // logits = h1all @ w_hy^T + b_y   (parallel GEMM, 16384 tiles of 64x64)
    for (int tile = bid; tile < 16384; tile += NB) {
        int mt = tile >> 3;            // 2048 m-tiles over B*T rows (layout [t][b])
        int nt = tile & 7;             // 8 n-tiles over V=512
        int m0 = mt * 64, n0 = nt * 64;
        gemm64(sA, sB, 0, HH,
            [&](int r, int k) { return g_h1all[(size_t)(m0 + r) * HH + k]; },
            [&](int r, int k) { return w_hy[(n0 + r) * HH + k]; },
            [&](int m, int n, float4 v) {
                int row = m0 + m;
                int tt = row >> 7;       // t
                int b  = row & 127;      // batch
                int col = n0 + n;
                float4 bb = *(const float4*)(b_y + col);
                v.x += bb.x; v.y += bb.y; v.z += bb.z; v.w += bb.w;
                *(float4*)&out[((size_t)b * TT + tt) * VV + col] = v;
            });
    }
}

// ---------------- launch ----------------
extern "C" void kernel_launch(void* const* d_in, const int* in_sizes, int n_in,
                              void* d_out, int out_size) {
    const int*   ids   = (const int*)d_in[0];
    const float* emb   = (const float*)d_in[1];
    const float* w_xh0 = (const float*)d_in[2];
    const float* w_hh0 = (const float*)d_in[3];
    const float* b_h0  = (const float*)d_in[4];
    const float* w_xh1 = (const float*)d_in[5];
    const float* w_hh1 = (const float*)d_in[6];
    const float* b_h1  = (const float*)d_in[7];
    const float* w_hy  = (const float*)d_in[8];
    const float* b_y   = (const float*)d_in[9];
    float* out = (float*)d_out;

    rnn_persistent_kernel<<<NB, NT>>>(ids, emb, w_xh0, w_hh0, b_h0,
                                      w_xh1, w_hh1, b_h1, w_hy, b_y,
                                      out, (long long)out_size);
}

// round 6
// speedup vs baseline: 2.7880x; 2.7880x over previous
#include <cuda_runtime.h>
#include <cuda_bf16.h>
#include <cstdint>

#define BB 128
#define TT 1024
#define EE 512
#define HH 1024
#define VV 512
#define NB 128
#define NT 256
#define BH (BB*HH)

#define SLAB_A 16384                 // per-term A slab: 128 rows x 128B
#define SLAB_B 8192                  // per-term B slab: 64 rows x 128B
#define B_OFF  (2*SLAB_A)
#define BUFB   (2*SLAB_A + 2*SLAB_B) // 49152 per pipeline buffer
#define DYNB   (2*BUFB + 1024)
#define REDS   66                    // smem reduction row stride (floats)

// ---------------- persistent device scratch ----------------
__device__ __align__(16) float g_tokproj[VV * HH];
__device__ __align__(16) float g_P0p[2][BH];
__device__ __align__(16) float g_P1p[4][BH];
__device__ __align__(16) float g_h0f[BH];
__device__ __align__(16) __nv_bfloat16 g_h0sp[2][BH];
__device__ __align__(16) __nv_bfloat16 g_h1cur[2][BH];
__device__ __align__(16) __nv_bfloat16 g_h1sp[2][(size_t)TT * BH];
__device__ __align__(16) __nv_bfloat16 g_w0sp[2][HH * HH];   // w_hh0 splits
__device__ __align__(16) __nv_bfloat16 g_w1sp[2][HH * HH];   // w_xh1 splits
__device__ __align__(16) __nv_bfloat16 g_w2sp[2][HH * HH];   // w_hh1 splits
__device__ __align__(16) __nv_bfloat16 g_wysp[2][VV * HH];   // w_hy splits
__device__ unsigned long long g_arrive;
__device__ unsigned long long g_epoch[NB];

// ---------------- helpers ----------------
__device__ __forceinline__ uint32_t smem_u32(const void* p) {
    uint32_t a;
    asm("{ .reg .u64 t; cvta.to.shared.u64 t, %1; cvt.u32.u64 %0, t; }" : "=r"(a) : "l"(p));
    return a;
}
__device__ __forceinline__ void cp16(uint32_t dst, const void* src) {
    asm volatile("cp.async.cg.shared.global [%0], [%1], 16;" :: "r"(dst), "l"(src) : "memory");
}
#define CP_COMMIT() asm volatile("cp.async.commit_group;" ::: "memory")
#define LDSM4(r, a) \
    asm volatile("ldmatrix.sync.aligned.m8n8.x4.shared.b16 {%0,%1,%2,%3}, [%4];" \
        : "=r"((r)[0]), "=r"((r)[1]), "=r"((r)[2]), "=r"((r)[3]) : "r"(a))
#define MMA16816(c, a, b0r, b1r) \
    asm volatile("mma.sync.aligned.m16n8k16.row.col.f32.bf16.bf16.f32 " \
        "{%0,%1,%2,%3}, {%4,%5,%6,%7}, {%8,%9}, {%0,%1,%2,%3};" \
        : "+f"((c)[0]), "+f"((c)[1]), "+f"((c)[2]), "+f"((c)[3]) \
        : "r"((a)[0]), "r"((a)[1]), "r"((a)[2]), "r"((a)[3]), "r"(b0r), "r"(b1r))

// ---------------- grid barrier (replay-safe) ----------------
__device__ __forceinline__ void grid_bar(unsigned long long& epoch) {
    __syncthreads();
    if (threadIdx.x == 0) {
        __threadfence();
        atomicAdd(&g_arrive, 1ULL);
        epoch += (unsigned long long)NB;
        while (*(volatile unsigned long long*)&g_arrive < epoch) { __nanosleep(64); }
        __threadfence();
    }
    __syncthreads();
}

// ---------------- bf16x2 split ----------------
__device__ __forceinline__ void split2(float x, __nv_bfloat16& d0, __nv_bfloat16& d1) {
    __nv_bfloat16 b0 = __float2bfloat16(x);
    d0 = b0;
    d1 = __float2bfloat16(x - __bfloat162float(b0));
}

// ---------------- SIMT fp32 64x64 GEMM (tokproj prologue only) ----------------
template <typename LA, typename LB, typename ST>
__device__ __forceinline__ void gemm64(float* sA, float* sB, int kend, LA la, LB lb, ST st) {
    const int tid = threadIdx.x;
    const int tx = tid & 15, ty = tid >> 4;
    float acc[4][4];
#pragma unroll
    for (int i = 0; i < 4; i++)
#pragma unroll
        for (int j = 0; j < 4; j++) acc[i][j] = 0.f;
    for (int k0 = 0; k0 < kend; k0 += 32) {
#pragma unroll
        for (int i = 0; i < 8; i++) {
            int idx = tid + i * NT;
            int k = idx & 31, r = idx >> 5;
            sA[k * 68 + r] = la(r, k0 + k);
            sB[k * 68 + r] = lb(r, k0 + k);
        }
        __syncthreads();
#pragma unroll
        for (int kk = 0; kk < 32; kk++) {
            float4 a = *(const float4*)(sA + kk * 68 + 4 * ty);
            float4 b = *(const float4*)(sB + kk * 68 + 4 * tx);
            float av[4] = {a.x, a.y, a.z, a.w};
            float bv[4] = {b.x, b.y, b.z, b.w};
#pragma unroll
            for (int i = 0; i < 4; i++)
#pragma unroll
                for (int j = 0; j < 4; j++) acc[i][j] = fmaf(av[i], bv[j], acc[i][j]);
        }
        __syncthreads();
    }
#pragma unroll
    for (int i = 0; i < 4; i++)
        st(4 * ty + i, 4 * tx, make_float4(acc[i][0], acc[i][1], acc[i][2], acc[i][3]));
}

// ---------------- tensor-core job: D[128,64] = sum_pairs A@B^T over K ----------------
// A terms: rows 0..127 stride HH; B terms: rows n0..n0+63 stride HH.
// 8 warps: 2(M) x 2(N) spatial x 2 K-split; smem reduction; epi(row, col, v0, v1).
template <typename EPI>
__device__ __forceinline__ void mma_job(
    const __nv_bfloat16* __restrict__ A0, const __nv_bfloat16* __restrict__ A1,
    const __nv_bfloat16* __restrict__ B0, const __nv_bfloat16* __restrict__ B1,
    int n0, int kglob0, int nchunk, uint32_t sb, EPI epi)
{
    const int tid = threadIdx.x;
    const int lane = tid & 31;
    const int warp = tid >> 5;
    const int wm = (warp >> 1) & 1, wn = warp & 1, ksub = warp >> 2;

    float acc[4][4][4];
#pragma unroll
    for (int a = 0; a < 4; a++)
#pragma unroll
        for (int b = 0; b < 4; b++)
#pragma unroll
            for (int c = 0; c < 4; c++) acc[a][b][c] = 0.f;

    auto stage = [&](int c) {
        const int kg = kglob0 + c * 64;
        const uint32_t base = sb + (c & 1) * BUFB;
#pragma unroll
        for (int it = 0; it < 12; it++) {
            int id = tid + it * NT;                 // 0..3071
            if (id < 2048) {                        // A: 2 terms x 128 rows x 8 segs
                int i = id >> 10, rem = id & 1023, r = rem >> 3, seg = rem & 7;
                const __nv_bfloat16* s = (i ? A1 : A0) + (size_t)r * HH + kg + seg * 8;
                cp16(base + i * SLAB_A + r * 128 + ((seg ^ (r & 7)) << 4), s);
            } else {                                // B: 2 terms x 64 rows x 8 segs
                int id2 = id - 2048;
                int j = id2 >> 9, rem = id2 & 511, r = rem >> 3, seg = rem & 7;
                const __nv_bfloat16* s = (j ? B1 : B0) + (size_t)(n0 + r) * HH + kg + seg * 8;
                cp16(base + B_OFF + j * SLAB_B + r * 128 + ((seg ^ (r & 7)) << 4), s);
            }
        }
        CP_COMMIT();
    };

    stage(0);
    for (int c = 0; c < nchunk; c++) {
        if (c + 1 < nchunk) {
            stage(c + 1);
            asm volatile("cp.async.wait_group 1;" ::: "memory");
        } else {
            asm volatile("cp.async.wait_group 0;" ::: "memory");
        }
        __syncthreads();
        const uint32_t base = sb + (c & 1) * BUFB;
#pragma unroll
        for (int kk = 0; kk < 2; kk++) {
            const int kki = ksub * 2 + kk;          // k16 index 0..3 within chunk
            uint32_t af[2][4][4];
#pragma unroll
            for (int tm = 0; tm < 2; tm++)
#pragma unroll
                for (int mt = 0; mt < 4; mt++) {
                    int row = wm * 64 + mt * 16 + (lane & 15);
                    int ch = kki * 2 + (lane >> 4);
                    LDSM4(af[tm][mt], base + tm * SLAB_A + row * 128 + ((ch ^ (row & 7)) << 4));
                }
#pragma unroll
            for (int j = 0; j < 2; j++) {
                uint32_t bf[8];
#pragma unroll
                for (int q = 0; q < 2; q++) {
                    int nrow = wn * 32 + q * 16 + (lane & 7) + ((lane & 16) ? 8 : 0);
                    int ch = kki * 2 + ((lane >> 3) & 1);
                    LDSM4(&bf[q * 4],
                          base + B_OFF + j * SLAB_B + nrow * 128 + ((ch ^ (nrow & 7)) << 4));
                }
                const int ni = (j == 0) ? 2 : 1;    // pairs: a0b0, a1b0, a0b1
#pragma unroll
                for (int i = 0; i < 2; i++) {
                    if (i >= ni) break;
#pragma unroll
                    for (int mt = 0; mt < 4; mt++)
#pragma unroll
                        for (int nt = 0; nt < 4; nt++) {
                            int q = nt >> 1, o = (nt & 1) * 2;
                            MMA16816(acc[mt][nt], af[i][mt], bf[q * 4 + o], bf[q * 4 + o + 1]);
                        }
                }
            }
        }
        __syncthreads();
    }

    // K-split reduction via smem (red area overlaps buffer 0 — all compute done)
    if (ksub == 1) {
#pragma unroll
        for (int mt = 0; mt < 4; mt++)
#pragma unroll
            for (int nt = 0; nt < 4; nt++) {
                int r = wm * 64 + mt * 16 + (lane >> 2);
                int cc = wn * 32 + nt * 8 + (lane & 3) * 2;
                asm volatile("st.shared.v2.f32 [%0], {%1,%2};"
                    :: "r"(sb + (uint32_t)(r * REDS + cc) * 4),
                       "f"(acc[mt][nt][0]), "f"(acc[mt][nt][1]) : "memory");
                asm volatile("st.shared.v2.f32 [%0], {%1,%2};"
                    :: "r"(sb + (uint32_t)((r + 8) * REDS + cc) * 4),
                       "f"(acc[mt][nt][2]), "f"(acc[mt][nt][3]) : "memory");
            }
    }
    __syncthreads();
    if (ksub == 0) {
#pragma unroll
        for (int mt = 0; mt < 4; mt++)
#pragma unroll
            for (int nt = 0; nt < 4; nt++) {
                int r = wm * 64 + mt * 16 + (lane >> 2);
                int cc = wn * 32 + nt * 8 + (lane & 3) * 2;
                float x0, x1, y0, y1;
                asm volatile("ld.shared.v2.f32 {%0,%1}, [%2];" : "=f"(x0), "=f"(x1)
                    : "r"(sb + (uint32_t)(r * REDS + cc) * 4));
                asm volatile("ld.shared.v2.f32 {%0,%1}, [%2];" : "=f"(y0), "=f"(y1)
                    : "r"(sb + (uint32_t)((r + 8) * REDS + cc) * 4));
                epi(r, cc, acc[mt][nt][0] + x0, acc[mt][nt][1] + x1);
                epi(r + 8, cc, acc[mt][nt][2] + y0, acc[mt][nt][3] + y1);
            }
    }
    __syncthreads();
}

// ---------------- main persistent kernel ----------------
__global__ void __launch_bounds__(NT, 1) rnn_mma_kernel(
    const int*   __restrict__ ids,
    const float* __restrict__ emb,
    const float* __restrict__ w_xh0,
    const float* __restrict__ w_hh0,
    const float* __restrict__ b_h0,
    const float* __restrict__ w_xh1,
    const float* __restrict__ w_hh1,
    const float* __restrict__ b_h1,
    const float* __restrict__ w_hy,
    const float* __restrict__ b_y,
    float* __restrict__ out,
    long long out_size)
{
    extern __shared__ __align__(16) char dynsm[];
    const int bid = blockIdx.x;
    const int tid = threadIdx.x;
    const uint32_t dyn = (smem_u32(dynsm) + 1023u) & ~1023u;

    unsigned long long epoch = 0;
    if (tid == 0) epoch = g_epoch[bid];

    // ============ prologue ============
    {   // bf16x2 weight splits (grid-strided; all L2/DRAM resident)
        const float* W[4] = {w_hh0, w_xh1, w_hh1, w_hy};
        __nv_bfloat16* S0[4] = {g_w0sp[0], g_w1sp[0], g_w2sp[0], g_wysp[0]};
        __nv_bfloat16* S1[4] = {g_w0sp[1], g_w1sp[1], g_w2sp[1], g_wysp[1]};
        const int SZ[4] = {HH * HH, HH * HH, HH * HH, VV * HH};
#pragma unroll
        for (int w = 0; w < 4; w++)
            for (int i = bid * NT + tid; i < SZ[w]; i += NB * NT)
                split2(W[w][i], S0[w][i], S1[w][i]);
        for (int i = bid * NT + tid; i < BH; i += NB * NT) {   // h1_{-1} = 0
            g_h1cur[0][i] = __float2bfloat16(0.f);
            g_h1cur[1][i] = __float2bfloat16(0.f);
        }
    }
    {   // tokproj[v][h] = b_h0[h] + emb[v] . w_xh0[h]
        float* sA = (float*)dynsm;
        float* sB = sA + 32 * 68;
        int m0 = (bid & 7) * 64, n0t = (bid >> 3) * 64;
        gemm64(sA, sB, EE,
            [&](int r, int k) { return emb[(m0 + r) * EE + k]; },
            [&](int r, int k) { return w_xh0[(n0t + r) * EE + k]; },
            [&](int m, int n, float4 v) {
                int col = n0t + n;
                float4 bb = *(const float4*)(b_h0 + col);
                v.x += bb.x; v.y += bb.y; v.z += bb.z; v.w += bb.w;
                *(float4*)(g_tokproj + (size_t)(m0 + m) * HH + col) = v;
            });
    }
    grid_bar(epoch);

    // ============ sequential loop ============
    for (int t = 0; t < TT; t++) {
        // ---- E phase: block = batch row; finalize h1_{t-1}, h0_t; emit splits ----
        {
            const int id_tok = ids[bid * TT + t];
            const float* tp = g_tokproj + (size_t)id_tok * HH;
            for (int i = tid; i < 1024; i += NT) {
                int idx = bid * 1024 + i;
                if (t > 0) {
                    float s1 = b_h1[i] + g_P1p[0][idx] + g_P1p[1][idx]
                                       + g_P1p[2][idx] + g_P1p[3][idx];
                    float v1 = tanhf(s1);
                    __nv_bfloat16 a, b; split2(v1, a, b);
                    g_h1cur[0][idx] = a; g_h1cur[1][idx] = b;
                    size_t hx = (size_t)(t - 1) * BH + idx;
                    g_h1sp[0][hx] = a; g_h1sp[1][hx] = b;
                }
                float s0 = tp[i];
                if (t > 0) s0 += g_P0p[0][idx] + g_P0p[1][idx];
                float v0 = tanhf(s0);
                if (t == TT - 1) g_h0f[idx] = v0;
                __nv_bfloat16 a, b; split2(v0, a, b);
                g_h0sp[0][idx] = a; g_h0sp[1][idx] = b;
            }
        }
        grid_bar(epoch);

        // ---- G phase: 96 tensor jobs ----
        if (bid < 32) {          // P0 = h0_t @ w_hh0^T (for step t+1)
            int ntile = bid & 15, kc = bid >> 4;
            int n0 = ntile * 64;
            float* pdst = g_P0p[kc];
            mma_job(g_h0sp[0], g_h0sp[1], g_w0sp[0], g_w0sp[1], n0, kc * 512, 8, dyn,
                [&](int r, int c, float v0, float v1) {
                    *(float2*)(pdst + (size_t)r * HH + n0 + c) = make_float2(v0, v1);
                });
        } else if (bid < 96) {   // P1 = h0_t @ w_xh1^T + h1_{t-1} @ w_hh1^T
            int j = bid - 32;
            int g = j >> 5, ntile = j & 15, kc = (j >> 4) & 1;
            int n0 = ntile * 64;
            float* pdst = g_P1p[g * 2 + kc];
            const __nv_bfloat16 *a0, *a1, *b0, *b1;
            if (g == 0) { a0 = g_h0sp[0];  a1 = g_h0sp[1];  b0 = g_w1sp[0]; b1 = g_w1sp[1]; }
            else        { a0 = g_h1cur[0]; a1 = g_h1cur[1]; b0 = g_w2sp[0]; b1 = g_w2sp[1]; }
            mma_job(a0, a1, b0, b1, n0, kc * 512, 8, dyn,
                [&](int r, int c, float v0, float v1) {
                    *(float2*)(pdst + (size_t)r * HH + n0 + c) = make_float2(v0, v1);
                });
        }
        grid_bar(epoch);
    }

    // ============ final E: h1_{T-1} + final states ============
    {
        const long long full = (long long)BB * TT * VV + 2LL * BB * HH;
        for (int i = tid; i < 1024; i += NT) {
            int idx = bid * 1024 + i;
            float s1 = b_h1[i] + g_P1p[0][idx] + g_P1p[1][idx]
                               + g_P1p[2][idx] + g_P1p[3][idx];
            float v1 = tanhf(s1);
            __nv_bfloat16 a, b; split2(v1, a, b);
            size_t hx = (size_t)(TT - 1) * BH + idx;
            g_h1sp[0][hx] = a; g_h1sp[1][hx] = b;
            if (out_size >= full) {
                out[(size_t)BB * TT * VV + idx] = g_h0f[idx];
                out[(size_t)BB * TT * VV + BH + idx] = v1;
            }
        }
    }
    grid_bar(epoch);
    if (tid == 0) g_epoch[bid] = epoch;

    // ============ logits: h1all @ w_hy^T + b_y (8192 tensor jobs) ============
    for (int jj = 0; jj < 64; jj++) {
        int job = bid * 64 + jj;
        int tj = job >> 3, nt = job & 7, n0 = nt * 64;
        const __nv_bfloat16* A0 = g_h1sp[0] + (size_t)tj * BH;
        const __nv_bfloat16* A1 = g_h1sp[1] + (size_t)tj * BH;
        mma_job(A0, A1, g_wysp[0], g_wysp[1], n0, 0, 16, dyn,
            [&](int r, int c, float v0, float v1) {
                int col = n0 + c;
                float2 by = *(const float2*)(b_y + col);
                *(float2*)(out + ((size_t)r * TT + tj) * VV + col) =
                    make_float2(v0 + by.x, v1 + by.y);
            });
    }
}

// ---------------- launch ----------------
extern "C" void kernel_launch(void* const* d_in, const int* in_sizes, int n_in,
                              void* d_out, int out_size) {
    const int*   ids   = (const int*)d_in[0];
    const float* emb   = (const float*)d_in[1];
    const float* w_xh0 = (const float*)d_in[2];
    const float* w_hh0 = (const float*)d_in[3];
    const float* b_h0  = (const float*)d_in[4];
    const float* w_xh1 = (const float*)d_in[5];
    const float* w_hh1 = (const float*)d_in[6];
    const float* b_h1  = (const float*)d_in[7];
    const float* w_hy  = (const float*)d_in[8];
    const float* b_y   = (const float*)d_in[9];
    float* out = (float*)d_out;

    cudaFuncSetAttribute(rnn_mma_kernel, cudaFuncAttributeMaxDynamicSharedMemorySize, DYNB);
    rnn_mma_kernel<<<NB, NT, DYNB>>>(ids, emb, w_xh0, w_hh0, b_h0,
                                     w_xh1, w_hh1, b_h1, w_hy, b_y,
                                     out, (long long)out_size);
}

// round 7
// speedup vs baseline: 3.5668x; 1.2793x over previous
#include <cuda_runtime.h>
#include <cuda_bf16.h>
#include <cstdint>

#define BB 128
#define TT 1024
#define EE 512
#define HH 1024
#define VV 512
#define NB 128
#define NT 256
#define BH (BB*HH)
#define BTV ((size_t)BB*TT*VV)

#define SLAB_B 8192            // one B chunk-term: 64 rows x 128B
#define AB0    131072          // A staging starts after persistent B (8 chunks x 2 terms x 8KB)
#define ABSZ   32768           // A buffer: 2 terms x 128 rows x 128B
#define DYNB   (AB0 + 2*ABSZ)  // 196608
#define DYNB_ALLOC (DYNB + 1024)

// ---------------- persistent device scratch ----------------
__device__ __align__(16) float g_tokproj[VV * HH];
__device__ __align__(16) float g_P0p[2][BH];
__device__ __align__(16) float g_P1p[4][BH];
__device__ __align__(16) float g_Py[4][BB * VV];
__device__ __align__(16) float g_h0f[BH];
__device__ __align__(16) __nv_bfloat16 g_h0sp[2][BH];
__device__ __align__(16) __nv_bfloat16 g_h1cur[2][BH];
__device__ __align__(16) __nv_bfloat16 g_w0sp[2][HH * HH];   // w_hh0
__device__ __align__(16) __nv_bfloat16 g_w1sp[2][HH * HH];   // w_xh1
__device__ __align__(16) __nv_bfloat16 g_w2sp[2][HH * HH];   // w_hh1
__device__ __align__(16) __nv_bfloat16 g_wysp[2][VV * HH];   // w_hy
__device__ unsigned long long g_arr8[8];
__device__ unsigned long long g_epoch[NB];

// ---------------- helpers ----------------
__device__ __forceinline__ uint32_t smem_u32(const void* p) {
    uint32_t a;
    asm("{ .reg .u64 t; cvta.to.shared.u64 t, %1; cvt.u32.u64 %0, t; }" : "=r"(a) : "l"(p));
    return a;
}
__device__ __forceinline__ void cp16(uint32_t dst, const void* src) {
    asm volatile("cp.async.cg.shared.global [%0], [%1], 16;" :: "r"(dst), "l"(src) : "memory");
}
#define CP_COMMIT() asm volatile("cp.async.commit_group;" ::: "memory")
#define STS128(a, x, y, z, w) \
    asm volatile("st.shared.v4.b32 [%0], {%1,%2,%3,%4};" \
                 :: "r"(a), "r"(x), "r"(y), "r"(z), "r"(w) : "memory")
#define LDSM4(r, a) \
    asm volatile("ldmatrix.sync.aligned.m8n8.x4.shared.b16 {%0,%1,%2,%3}, [%4];" \
        : "=r"((r)[0]), "=r"((r)[1]), "=r"((r)[2]), "=r"((r)[3]) : "r"(a))
#define MMA16816(c, a, b0r, b1r) \
    asm volatile("mma.sync.aligned.m16n8k16.row.col.f32.bf16.bf16.f32 " \
        "{%0,%1,%2,%3}, {%4,%5,%6,%7}, {%8,%9}, {%0,%1,%2,%3};" \
        : "+f"((c)[0]), "+f"((c)[1]), "+f"((c)[2]), "+f"((c)[3]) \
        : "r"((a)[0]), "r"((a)[1]), "r"((a)[2]), "r"((a)[3]), "r"(b0r), "r"(b1r))

// ---------------- grid barrier: 8 counters, replay-safe ----------------
__device__ __forceinline__ void grid_bar(unsigned long long& epoch) {
    __syncthreads();
    if (threadIdx.x == 0) {
        __threadfence();
        atomicAdd(&g_arr8[blockIdx.x & 7], 1ULL);
        epoch += (unsigned long long)NB;
        for (;;) {
            unsigned long long s = 0;
#pragma unroll
            for (int i = 0; i < 8; i++) s += *(volatile unsigned long long*)&g_arr8[i];
            if (s >= epoch) break;
            __nanosleep(32);
        }
        __threadfence();
    }
    __syncthreads();
}

// ---------------- bf16x2 split ----------------
__device__ __forceinline__ void split2(float x, __nv_bfloat16& d0, __nv_bfloat16& d1) {
    __nv_bfloat16 b0 = __float2bfloat16(x);
    d0 = b0;
    d1 = __float2bfloat16(x - __bfloat162float(b0));
}
__device__ __forceinline__ void st_split4(__nv_bfloat16* d0, __nv_bfloat16* d1,
                                          size_t idx, float4 v) {
    __nv_bfloat16 a0, b0, a1, b1, a2, b2, a3, b3;
    split2(v.x, a0, b0); split2(v.y, a1, b1);
    split2(v.z, a2, b2); split2(v.w, a3, b3);
    __nv_bfloat162 lo0(a0, a1), hi0(a2, a3), lo1(b0, b1), hi1(b2, b3);
    *(uint2*)(d0 + idx) = make_uint2(*(uint32_t*)&lo0, *(uint32_t*)&hi0);
    *(uint2*)(d1 + idx) = make_uint2(*(uint32_t*)&lo1, *(uint32_t*)&hi1);
}

// ---------------- SIMT fp32 64x64 GEMM (tokproj prologue only) ----------------
template <typename LA, typename LB, typename ST>
__device__ __forceinline__ void gemm64(float* sA, float* sB, int kend, LA la, LB lb, ST st) {
    const int tid = threadIdx.x;
    const int tx = tid & 15, ty = tid >> 4;
    float acc[4][4];
#pragma unroll
    for (int i = 0; i < 4; i++)
#pragma unroll
        for (int j = 0; j < 4; j++) acc[i][j] = 0.f;
    for (int k0 = 0; k0 < kend; k0 += 32) {
#pragma unroll
        for (int i = 0; i < 8; i++) {
            int idx = tid + i * NT;
            int k = idx & 31, r = idx >> 5;
            sA[k * 68 + r] = la(r, k0 + k);
            sB[k * 68 + r] = lb(r, k0 + k);
        }
        __syncthreads();
#pragma unroll
        for (int kk = 0; kk < 32; kk++) {
            float4 a = *(const float4*)(sA + kk * 68 + 4 * ty);
            float4 b = *(const float4*)(sB + kk * 68 + 4 * tx);
            float av[4] = {a.x, a.y, a.z, a.w};
            float bv[4] = {b.x, b.y, b.z, b.w};
#pragma unroll
            for (int i = 0; i < 4; i++)
#pragma unroll
                for (int j = 0; j < 4; j++) acc[i][j] = fmaf(av[i], bv[j], acc[i][j]);
        }
        __syncthreads();
    }
#pragma unroll
    for (int i = 0; i < 4; i++)
        st(4 * ty + i, 4 * tx, make_float4(acc[i][0], acc[i][1], acc[i][2], acc[i][3]));
}

// ---------------- tensor job: D[128,64] += 3-term A@B^T, B persistent in smem ----------------
// 8 warps = 4(M) x 2(N); warp tile 32x32; direct register epilogue. epi(row, col, v0, v1)
template <typename EPI>
__device__ __forceinline__ void mma_job(
    const __nv_bfloat16* __restrict__ A0, const __nv_bfloat16* __restrict__ A1,
    int kglob0, int nchunk, uint32_t dyn, EPI epi)
{
    const int tid = threadIdx.x;
    const int lane = tid & 31;
    const int warp = tid >> 5;
    const int wm = warp >> 1, wn = warp & 1;

    float acc[2][4][4];
#pragma unroll
    for (int a = 0; a < 2; a++)
#pragma unroll
        for (int b = 0; b < 4; b++)
#pragma unroll
            for (int c = 0; c < 4; c++) acc[a][b][c] = 0.f;

    auto stage = [&](int c) {
        const int kg = kglob0 + c * 64;
        const uint32_t ab = dyn + AB0 + (c & 1) * ABSZ;
#pragma unroll
        for (int it = 0; it < 8; it++) {
            int id = tid + it * NT;                 // 0..2047
            int i = id >> 10, rem = id & 1023, r = rem >> 3, seg = rem & 7;
            const __nv_bfloat16* s = (i ? A1 : A0) + (size_t)r * HH + kg + seg * 8;
            cp16(ab + i * 16384 + r * 128 + ((seg ^ (r & 7)) << 4), s);
        }
        CP_COMMIT();
    };

    stage(0);
    for (int c = 0; c < nchunk; c++) {
        if (c + 1 < nchunk) {
            stage(c + 1);
            asm volatile("cp.async.wait_group 1;" ::: "memory");
        } else {
            asm volatile("cp.async.wait_group 0;" ::: "memory");
        }
        __syncthreads();
        const uint32_t ab = dyn + AB0 + (c & 1) * ABSZ;
        const uint32_t pb = dyn + c * (2 * SLAB_B);
#pragma unroll
        for (int kk = 0; kk < 4; kk++) {
            uint32_t af[2][2][4];
#pragma unroll
            for (int tm = 0; tm < 2; tm++)
#pragma unroll
                for (int mt = 0; mt < 2; mt++) {
                    int row = wm * 32 + mt * 16 + (lane & 15);
                    int ch = kk * 2 + (lane >> 4);
                    LDSM4(af[tm][mt], ab + tm * 16384 + row * 128 + ((ch ^ (row & 7)) << 4));
                }
            uint32_t bf[2][8];
#pragma unroll
            for (int j = 0; j < 2; j++)
#pragma unroll
                for (int q = 0; q < 2; q++) {
                    int nrow = wn * 32 + q * 16 + (lane & 7) + ((lane & 16) ? 8 : 0);
                    int ch = kk * 2 + ((lane >> 3) & 1);
                    LDSM4(&bf[j][q * 4], pb + j * SLAB_B + nrow * 128 + ((ch ^ (nrow & 7)) << 4));
                }
#pragma unroll
            for (int j = 0; j < 2; j++) {
                const int ni = (j == 0) ? 2 : 1;    // terms: a0b0, a1b0, a0b1
#pragma unroll
                for (int i = 0; i < 2; i++) {
                    if (i >= ni) break;
#pragma unroll
                    for (int mt = 0; mt < 2; mt++)
#pragma unroll
                        for (int nt = 0; nt < 4; nt++) {
                            int q = nt >> 1, o = (nt & 1) * 2;
                            MMA16816(acc[mt][nt], af[i][mt], bf[j][q * 4 + o], bf[j][q * 4 + o + 1]);
                        }
                }
            }
        }
        __syncthreads();
    }
#pragma unroll
    for (int mt = 0; mt < 2; mt++)
#pragma unroll
        for (int nt = 0; nt < 4; nt++) {
            int r = wm * 32 + mt * 16 + (lane >> 2);
            int cc = wn * 32 + nt * 8 + (lane & 3) * 2;
            epi(r, cc, acc[mt][nt][0], acc[mt][nt][1]);
            epi(r + 8, cc, acc[mt][nt][2], acc[mt][nt][3]);
        }
}

// ---------------- main persistent kernel ----------------
__global__ void __launch_bounds__(NT, 1) rnn_mma_kernel(
    const int*   __restrict__ ids,
    const float* __restrict__ emb,
    const float* __restrict__ w_xh0,
    const float* __restrict__ w_hh0,
    const float* __restrict__ b_h0,
    const float* __restrict__ w_xh1,
    const float* __restrict__ w_hh1,
    const float* __restrict__ b_h1,
    const float* __restrict__ w_hy,
    const float* __restrict__ b_y,
    float* __restrict__ out,
    long long out_size)
{
    extern __shared__ __align__(16) char dynsm[];
    const int bid = blockIdx.x;
    const int tid = threadIdx.x;
    const uint32_t dyn = (smem_u32(dynsm) + 1023u) & ~1023u;
    const long long full = (long long)BTV + 2LL * BH;

    unsigned long long epoch = 0;
    if (tid == 0) epoch = g_epoch[bid];

    // ---- job assignment (fixed per block for the whole kernel) ----
    // role 0: bid 0..31   P0 = h0 @ w_hh0^T       (16 n-tiles x 2 kc, K=512)
    // role 1: bid 32..63  P1a = h0 @ w_xh1^T      (16 n x 2 kc)
    // role 2: bid 64..95  P1b = h1 @ w_hh1^T      (16 n x 2 kc)
    // role 3: bid 96..127 LOG = h1 @ w_hy^T       (8 n x 4 kc, K=256)
    int role, n0, kbeg, nch;
    const __nv_bfloat16 *Bs0, *Bs1;
    float* pdst;
    if (bid < 32) {
        role = 0; n0 = (bid & 15) * 64; int kc = bid >> 4;
        kbeg = kc * 512; nch = 8; Bs0 = g_w0sp[0]; Bs1 = g_w0sp[1]; pdst = g_P0p[kc];
    } else if (bid < 64) {
        role = 1; int j = bid - 32; n0 = (j & 15) * 64; int kc = j >> 4;
        kbeg = kc * 512; nch = 8; Bs0 = g_w1sp[0]; Bs1 = g_w1sp[1]; pdst = g_P1p[kc];
    } else if (bid < 96) {
        role = 2; int j = bid - 64; n0 = (j & 15) * 64; int kc = j >> 4;
        kbeg = kc * 512; nch = 8; Bs0 = g_w2sp[0]; Bs1 = g_w2sp[1]; pdst = g_P1p[2 + kc];
    } else {
        role = 3; int j = bid - 96; n0 = (j >> 2) * 64; int kc = j & 3;
        kbeg = kc * 256; nch = 4; Bs0 = g_wysp[0]; Bs1 = g_wysp[1]; pdst = g_Py[kc];
    }

    // ============ prologue ============
    {   // bf16x2 weight splits (grid-strided)
        const float* W[4] = {w_hh0, w_xh1, w_hh1, w_hy};
        __nv_bfloat16* S0[4] = {g_w0sp[0], g_w1sp[0], g_w2sp[0], g_wysp[0]};
        __nv_bfloat16* S1[4] = {g_w0sp[1], g_w1sp[1], g_w2sp[1], g_wysp[1]};
        const int SZ[4] = {HH * HH, HH * HH, HH * HH, VV * HH};
#pragma unroll
        for (int w = 0; w < 4; w++)
            for (int i = bid * NT + tid; i < SZ[w]; i += NB * NT)
                split2(W[w][i], S0[w][i], S1[w][i]);
        for (int i = bid * NT + tid; i < BH; i += NB * NT) {   // h1_{-1} = 0
            g_h1cur[0][i] = __float2bfloat16(0.f);
            g_h1cur[1][i] = __float2bfloat16(0.f);
        }
    }
    {   // tokproj[v][h] = b_h0[h] + emb[v] . w_xh0[h]
        float* sA = (float*)dynsm;
        float* sB = sA + 32 * 68;
        int m0 = (bid & 7) * 64, n0t = (bid >> 3) * 64;
        gemm64(sA, sB, EE,
            [&](int r, int k) { return emb[(m0 + r) * EE + k]; },
            [&](int r, int k) { return w_xh0[(n0t + r) * EE + k]; },
            [&](int m, int n, float4 v) {
                int col = n0t + n;
                float4 bb = *(const float4*)(b_h0 + col);
                v.x += bb.x; v.y += bb.y; v.z += bb.z; v.w += bb.w;
                *(float4*)(g_tokproj + (size_t)(m0 + m) * HH + col) = v;
            });
    }
    grid_bar(epoch);

    // ---- load persistent B slice into smem (once) ----
    {
        const int total = nch * 1024;   // nch chunks x 2 terms x 64 rows x 8 segs
        for (int x = tid; x < total; x += NT) {
            int c = x >> 10, rem = x & 1023;
            int jt = rem >> 9, r = (rem >> 3) & 63, seg = rem & 7;
            const __nv_bfloat16* s = (jt ? Bs1 : Bs0)
                + (size_t)(n0 + r) * HH + kbeg + c * 64 + seg * 8;
            uint4 v = *(const uint4*)s;
            STS128(dyn + (c * 2 + jt) * SLAB_B + r * 128 + ((seg ^ (r & 7)) << 4),
                   v.x, v.y, v.z, v.w);
        }
        __syncthreads();
    }

    // epilogue lambda: fp32 partials (row-major [b][h])
    auto epi_part = [&](int r, int c, float v0, float v1) {
        *(float2*)(pdst + (size_t)r * HH + n0 + c) = make_float2(v0, v1);
    };
    auto epi_log = [&](int r, int c, float v0, float v1) {
        *(float2*)(pdst + (size_t)r * VV + n0 + c) = make_float2(v0, v1);
    };

    // ============ pipelined loop: t = 0 .. TT (inclusive drain step) ============
    for (int t = 0; t <= TT; t++) {
        // ---- E phase (block = batch row bid) ----
        {
            const int i = tid * 4;
            const size_t idx = (size_t)bid * HH + i;
            if (t > 0) {       // finalize h1_{t-1}
                float4 a = *(const float4*)&g_P1p[0][idx];
                float4 b = *(const float4*)&g_P1p[1][idx];
                float4 c = *(const float4*)&g_P1p[2][idx];
                float4 d = *(const float4*)&g_P1p[3][idx];
                float4 bb = *(const float4*)(b_h1 + i);
                float4 v;
                v.x = tanhf(bb.x + a.x + b.x + c.x + d.x);
                v.y = tanhf(bb.y + a.y + b.y + c.y + d.y);
                v.z = tanhf(bb.z + a.z + b.z + c.z + d.z);
                v.w = tanhf(bb.w + a.w + b.w + c.w + d.w);
                st_split4(g_h1cur[0], g_h1cur[1], idx, v);
                if (t == TT && out_size >= full) {
                    *(float4*)&out[BTV + BH + idx] = v;   // final h1
                }
            }
            if (t < TT) {      // compute h0_t
                const int id_tok = ids[bid * TT + t];
                float4 s = *(const float4*)(g_tokproj + (size_t)id_tok * HH + i);
                if (t > 0) {
                    float4 a = *(const float4*)&g_P0p[0][idx];
                    float4 b = *(const float4*)&g_P0p[1][idx];
                    s.x += a.x + b.x; s.y += a.y + b.y;
                    s.z += a.z + b.z; s.w += a.w + b.w;
                }
                float4 v;
                v.x = tanhf(s.x); v.y = tanhf(s.y); v.z = tanhf(s.z); v.w = tanhf(s.w);
                if (t == TT - 1) *(float4*)&g_h0f[idx] = v;
                st_split4(g_h0sp[0], g_h0sp[1], idx, v);
            }
            if (t >= 2 && tid < 128) {   // reduce logits for step t-2
                int v0 = tid * 4;
                size_t pidx = (size_t)bid * VV + v0;
                float4 a = *(const float4*)&g_Py[0][pidx];
                float4 b = *(const float4*)&g_Py[1][pidx];
                float4 c = *(const float4*)&g_Py[2][pidx];
                float4 d = *(const float4*)&g_Py[3][pidx];
                float4 bb = *(const float4*)(b_y + v0);
                float4 r;
                r.x = bb.x + a.x + b.x + c.x + d.x;
                r.y = bb.y + a.y + b.y + c.y + d.y;
                r.z = bb.z + a.z + b.z + c.z + d.z;
                r.w = bb.w + a.w + b.w + c.w + d.w;
                *(float4*)&out[((size_t)bid * TT + (t - 2)) * VV + v0] = r;
            }
        }
        grid_bar(epoch);

        // ---- G phase ----
        if (role == 0) {
            if (t < TT - 1)
                mma_job(g_h0sp[0], g_h0sp[1], kbeg, nch, dyn, epi_part);
        } else if (role == 1) {
            if (t < TT)
                mma_job(g_h0sp[0], g_h0sp[1], kbeg, nch, dyn, epi_part);
        } else if (role == 2) {
            if (t < TT)
                mma_job(g_h1cur[0], g_h1cur[1], kbeg, nch, dyn, epi_part);
        } else {
            if (t >= 1)
                mma_job(g_h1cur[0], g_h1cur[1], kbeg, nch, dyn, epi_log);
        }
        grid_bar(epoch);
    }

    // ============ post-loop: reduce logits for t = TT-1; final h0 ============
    if (tid < 128) {
        int v0 = tid * 4;
        size_t pidx = (size_t)bid * VV + v0;
        float4 a = *(const float4*)&g_Py[0][pidx];
        float4 b = *(const float4*)&g_Py[1][pidx];
        float4 c = *(const float4*)&g_Py[2][pidx];
        float4 d = *(const float4*)&g_Py[3][pidx];
        float4 bb = *(const float4*)(b_y + v0);
        float4 r;
        r.x = bb.x + a.x + b.x + c.x + d.x;
        r.y = bb.y + a.y + b.y + c.y + d.y;
        r.z = bb.z + a.z + b.z + c.z + d.z;
        r.w = bb.w + a.w + b.w + c.w + d.w;
        *(float4*)&out[((size_t)bid * TT + (TT - 1)) * VV + v0] = r;
    }
    if (out_size >= full) {
        const int i = tid * 4;
        const size_t idx = (size_t)bid * HH + i;
        *(float4*)&out[BTV + idx] = *(const float4*)&g_h0f[idx];   // final h0
    }
    if (tid == 0) g_epoch[bid] = epoch;
}

// ---------------- launch ----------------
extern "C" void kernel_launch(void* const* d_in, const int* in_sizes, int n_in,
                              void* d_out, int out_size) {
    const int*   ids   = (const int*)d_in[0];
    const float* emb   = (const float*)d_in[1];
    const float* w_xh0 = (const float*)d_in[2];
    const float* w_hh0 = (const float*)d_in[3];
    const float* b_h0  = (const float*)d_in[4];
    const float* w_xh1 = (const float*)d_in[5];
    const float* w_hh1 = (const float*)d_in[6];
    const float* b_h1  = (const float*)d_in[7];
    const float* w_hy  = (const float*)d_in[8];
    const float* b_y   = (const float*)d_in[9];
    float* out = (float*)d_out;

    cudaFuncSetAttribute(rnn_mma_kernel, cudaFuncAttributeMaxDynamicSharedMemorySize,
                         DYNB_ALLOC);
    rnn_mma_kernel<<<NB, NT, DYNB_ALLOC>>>(ids, emb, w_xh0, w_hh0, b_h0,
                                           w_xh1, w_hh1, b_h1, w_hy, b_y,
                                           out, (long long)out_size);
}